// round 1
// baseline (speedup 1.0000x reference)
#include <cuda_runtime.h>
#include <cstdint>
#include <cstddef>

#define A_   8
#define Bsz  32768
#define H_   128
#define EPSB 1e-5f

// ---------------- static scratch (no runtime allocation) ----------------
__device__ float g_part[8 * 32 * 160 * 2];
__device__ float g_mean[8 * 160];
__device__ float g_istd[8 * 160];
__device__ float g_Wk[128 * 128];
__device__ float g_Ws[128 * 128];
__device__ float g_Wv[128 * 128];
__device__ float g_aenc[(size_t)A_ * Bsz * H_];
__device__ float g_keys[(size_t)A_ * Bsz * H_];
__device__ float g_sels[(size_t)A_ * Bsz * H_];
__device__ float g_vals[(size_t)A_ * Bsz * H_];
__device__ float g_ci  [(size_t)A_ * Bsz * 256];   // [sa_enc | attended]
__device__ float g_h   [(size_t)A_ * Bsz * H_];

__device__ __forceinline__ float lrelu(float x) { return fmaxf(x, 0.01f * x); }

// ---------------- packed f32x2 helpers (Blackwell FFMA2) ----------------
__device__ __forceinline__ unsigned long long pk2(float x, float y) {
    unsigned long long r;
    asm("mov.b64 %0, {%1, %2};" : "=l"(r) : "f"(x), "f"(y));
    return r;
}
__device__ __forceinline__ float2 upk2(unsigned long long v) {
    float lo, hi;
    asm("mov.b64 {%0, %1}, %2;" : "=f"(lo), "=f"(hi) : "l"(v));
    return make_float2(lo, hi);
}
__device__ __forceinline__ void ffma2(unsigned long long& d,
                                      unsigned long long a, unsigned long long b) {
    asm("fma.rn.f32x2 %0, %1, %2, %0;" : "+l"(d) : "l"(a), "l"(b));
}

// ---------------- BatchNorm stats: partial sums ----------------
// grid (32 chunks, 8 agents), 320 threads. Each block: 1024 rows, 160 features.
__global__ void bn_partial_k(const float* __restrict__ states,
                             const float* __restrict__ actions) {
    int a = blockIdx.y, chunk = blockIdx.x;
    int t = threadIdx.x;
    int f = t % 160, r0 = t / 160;   // r0 in {0,1}
    size_t sb = (size_t)a * Bsz * 128, ab = (size_t)a * Bsz * 32;
    int row0 = chunk * 1024;
    float s = 0.f, s2 = 0.f;
    if (f < 128) {
        const float* p = states + sb + (size_t)(row0 + r0) * 128 + f;
        #pragma unroll 4
        for (int r = 0; r < 512; r++) { float v = *p; p += 256; s += v; s2 += v * v; }
    } else {
        const float* p = actions + ab + (size_t)(row0 + r0) * 32 + (f - 128);
        #pragma unroll 4
        for (int r = 0; r < 512; r++) { float v = *p; p += 64; s += v; s2 += v * v; }
    }
    __shared__ float sh[640];
    sh[t] = s; sh[320 + t] = s2;
    __syncthreads();
    if (t < 160) {
        float ss = sh[t] + sh[t + 160];
        float qq = sh[320 + t] + sh[320 + t + 160];
        int o = ((a * 32 + chunk) * 160 + t) * 2;
        g_part[o] = ss; g_part[o + 1] = qq;
    }
}

// grid 8, 160 threads: reduce chunks -> mean/istd
__global__ void bn_final_k() {
    int a = blockIdx.x, f = threadIdx.x;
    float s = 0.f, s2 = 0.f;
    for (int c = 0; c < 32; c++) {
        int o = ((a * 32 + c) * 160 + f) * 2;
        s += g_part[o]; s2 += g_part[o + 1];
    }
    float m = s * (1.f / 32768.f);
    float v = s2 * (1.f / 32768.f) - m * m;
    g_mean[a * 160 + f] = m;
    g_istd[a * 160 + f] = rsqrtf(v + EPSB);
}

// pack head weights [K,H,D] -> [H, K*D]
__global__ void pack_k(const float* __restrict__ kw,
                       const float* __restrict__ sw,
                       const float* __restrict__ vw) {
    int idx = blockIdx.x * 256 + threadIdx.x;           // < 49152
    int which = idx >> 14;
    int rem = idx & 16383;
    int h = rem >> 7, kd = rem & 127;
    int k = kd >> 5, d = kd & 31;
    const float* src = (which == 0) ? kw : (which == 1) ? sw : vw;
    float v = src[(k * 128 + h) * 32 + d];
    float* dst = (which == 0) ? g_Wk : (which == 1) ? g_Ws : g_Wv;
    dst[h * 128 + kd] = v;
}

// ---------------- generic tiled SGEMM with generators + epilogues ----------------
// C[a][m][n] = epi( sum_k A[a][m][k] * W[a][k][n] + bias[n] )
// src_mode: 0 direct (Abase, lda), 1 BN(concat states|actions) K=160, 2 BN(actions) K=32
// epi_mode: 0 none, 1 bias + leaky-relu
#define BM 128
#define BN 128
#define BK 16
#define BMP 132

#define LOADA(reg, rr, cc, k0) {                                               \
    int k_ = (k0) + (cc); int m_ = m0 + (rr); float4 v_;                        \
    if (src_mode == 1) {                                                        \
        if (k_ < 128) v_ = *(const float4*)(states + sb + (size_t)m_ * 128 + k_);\
        else          v_ = *(const float4*)(actions + ab + (size_t)m_ * 32 + (k_ - 128)); \
        v_.x = (v_.x - mp[k_    ]) * ip[k_    ];                                \
        v_.y = (v_.y - mp[k_ + 1]) * ip[k_ + 1];                                \
        v_.z = (v_.z - mp[k_ + 2]) * ip[k_ + 2];                                \
        v_.w = (v_.w - mp[k_ + 3]) * ip[k_ + 3];                                \
    } else if (src_mode == 2) {                                                 \
        v_ = *(const float4*)(actions + ab + (size_t)m_ * 32 + k_);             \
        v_.x = (v_.x - mp[128 + k_]) * ip[128 + k_];                            \
        v_.y = (v_.y - mp[129 + k_]) * ip[129 + k_];                            \
        v_.z = (v_.z - mp[130 + k_]) * ip[130 + k_];                            \
        v_.w = (v_.w - mp[131 + k_]) * ip[131 + k_];                            \
    } else {                                                                    \
        v_ = *(const float4*)(Abase + Ao + (size_t)m_ * lda + k_);              \
    }                                                                           \
    reg = v_; }

#define LOADB(reg, rr, cc, k0) { reg = *(const float4*)(Wp + (size_t)((k0) + (rr)) * 128 + (cc)); }

__global__ __launch_bounds__(256, 2) void gemm_k(
    const float* __restrict__ Abase, int lda,
    const float* __restrict__ states, const float* __restrict__ actions,
    const float* __restrict__ W, int wstride,
    const float* __restrict__ bias, int bstride,
    float* __restrict__ C, int ldc,
    int Kdim, int src_mode, int epi_mode) {

    __shared__ float As[BK][BMP];
    __shared__ float Bs[BK][BN];
    int a = blockIdx.z;
    int m0 = blockIdx.x * BM;
    int tid = threadIdx.x;
    int tx = tid & 15, ty = tid >> 4;

    const float* mp = g_mean + a * 160;
    const float* ip = g_istd + a * 160;
    const float* Wp = W + (size_t)a * wstride;
    size_t sb = (size_t)a * Bsz * 128;
    size_t ab = (size_t)a * Bsz * 32;
    size_t Ao = (size_t)a * Bsz * (size_t)lda;

    // per-thread staging coordinates (2 float4 each for A and B tiles)
    int r0 = tid >> 2,        c0 = (tid & 3) * 4;
    int r1 = (tid + 256) >> 2;
    int rb0 = tid >> 5,       cb0 = (tid & 31) * 4;
    int rb1 = rb0 + 8;

    unsigned long long acc[8][4];
    #pragma unroll
    for (int i = 0; i < 8; i++)
        #pragma unroll
        for (int j = 0; j < 4; j++) acc[i][j] = 0ULL;

    float4 pa0, pa1, pb0, pb1;
    int nk = Kdim / BK;

    LOADA(pa0, r0, c0, 0); LOADA(pa1, r1, c0, 0);
    LOADB(pb0, rb0, cb0, 0); LOADB(pb1, rb1, cb0, 0);

    for (int kb = 0; kb < nk; kb++) {
        As[c0 + 0][r0] = pa0.x; As[c0 + 1][r0] = pa0.y;
        As[c0 + 2][r0] = pa0.z; As[c0 + 3][r0] = pa0.w;
        As[c0 + 0][r1] = pa1.x; As[c0 + 1][r1] = pa1.y;
        As[c0 + 2][r1] = pa1.z; As[c0 + 3][r1] = pa1.w;
        *(float4*)&Bs[rb0][cb0] = pb0;
        *(float4*)&Bs[rb1][cb0] = pb1;
        __syncthreads();
        if (kb + 1 < nk) {
            int k0n = (kb + 1) * BK;
            LOADA(pa0, r0, c0, k0n); LOADA(pa1, r1, c0, k0n);
            LOADB(pb0, rb0, cb0, k0n); LOADB(pb1, rb1, cb0, k0n);
        }
        #pragma unroll
        for (int kk = 0; kk < BK; kk++) {
            float4 a0 = *(const float4*)&As[kk][ty * 8];
            float4 a1 = *(const float4*)&As[kk][ty * 8 + 4];
            float4 b0 = *(const float4*)&Bs[kk][tx * 8];
            float4 b1 = *(const float4*)&Bs[kk][tx * 8 + 4];
            unsigned long long bp[4] = { pk2(b0.x, b0.y), pk2(b0.z, b0.w),
                                         pk2(b1.x, b1.y), pk2(b1.z, b1.w) };
            float av[8] = { a0.x, a0.y, a0.z, a0.w, a1.x, a1.y, a1.z, a1.w };
            #pragma unroll
            for (int i = 0; i < 8; i++) {
                unsigned long long ad = pk2(av[i], av[i]);
                #pragma unroll
                for (int j = 0; j < 4; j++) ffma2(acc[i][j], ad, bp[j]);
            }
        }
        __syncthreads();
    }

    size_t Co = (size_t)a * Bsz * (size_t)ldc;
    #pragma unroll
    for (int i = 0; i < 8; i++) {
        int m = m0 + ty * 8 + i;
        float* crow = C + Co + (size_t)m * ldc + tx * 8;
        #pragma unroll
        for (int j = 0; j < 4; j++) {
            float2 v = upk2(acc[i][j]);
            if (epi_mode == 1) {
                int n = tx * 8 + j * 2;
                v.x = lrelu(v.x + bias[a * bstride + n]);
                v.y = lrelu(v.y + bias[a * bstride + n + 1]);
            }
            *(float2*)(crow + j * 2) = v;
        }
    }
}

// ---------------- attention: 16 batch elts x 8 agents per block ----------------
__global__ __launch_bounds__(128) void attn_k() {
    __shared__ float sA[128 * 33];   // sels, then reused for vals
    __shared__ float sK[128 * 33];   // keys
    int t = threadIdx.x;
    int b0 = blockIdx.x * 16;
    int bl = t >> 3, iq = t & 7;     // compute coords
    int lbl = t >> 3, lf4 = t & 7;   // load coords

    for (int kh = 0; kh < 4; kh++) {
        __syncthreads();
        #pragma unroll
        for (int ag = 0; ag < 8; ag++) {
            size_t off = ((size_t)ag * Bsz + b0 + lbl) * 128 + kh * 32 + lf4 * 4;
            float4 v = *(const float4*)(g_sels + off);
            int base = (lbl * 8 + ag) * 33 + lf4 * 4;
            sA[base] = v.x; sA[base + 1] = v.y; sA[base + 2] = v.z; sA[base + 3] = v.w;
            float4 w = *(const float4*)(g_keys + off);
            sK[base] = w.x; sK[base + 1] = w.y; sK[base + 2] = w.z; sK[base + 3] = w.w;
        }
        __syncthreads();

        float sv[32];
        #pragma unroll
        for (int d = 0; d < 32; d++) sv[d] = sA[(bl * 8 + iq) * 33 + d];
        float p[8];
        #pragma unroll
        for (int j = 0; j < 8; j++) {
            float acc = 0.f;
            #pragma unroll
            for (int d = 0; d < 32; d++) acc += sv[d] * sK[(bl * 8 + j) * 33 + d];
            p[j] = acc * 0.17677669529663687f;   // 1/sqrt(32)
        }
        float mx = -1e30f;
        #pragma unroll
        for (int j = 0; j < 8; j++) if (j != iq) mx = fmaxf(mx, p[j]);
        float sum = 0.f;
        #pragma unroll
        for (int j = 0; j < 8; j++) {
            p[j] = (j == iq) ? 0.f : __expf(p[j] - mx);
            sum += p[j];
        }
        float inv = 1.f / sum;

        __syncthreads();
        #pragma unroll
        for (int ag = 0; ag < 8; ag++) {
            size_t off = ((size_t)ag * Bsz + b0 + lbl) * 128 + kh * 32 + lf4 * 4;
            float4 v = *(const float4*)(g_vals + off);
            int base = (lbl * 8 + ag) * 33 + lf4 * 4;
            sA[base] = v.x; sA[base + 1] = v.y; sA[base + 2] = v.z; sA[base + 3] = v.w;
        }
        __syncthreads();

        float ov[32];
        #pragma unroll
        for (int d = 0; d < 32; d++) ov[d] = 0.f;
        #pragma unroll
        for (int j = 0; j < 8; j++) {
            float pj = p[j] * inv;
            #pragma unroll
            for (int d = 0; d < 32; d++) ov[d] += pj * sA[(bl * 8 + j) * 33 + d];
        }
        float* dst = g_ci + ((size_t)iq * Bsz + b0 + bl) * 256 + 128 + kh * 32;
        #pragma unroll
        for (int d4 = 0; d4 < 8; d4++)
            *(float4*)(dst + d4 * 4) =
                make_float4(ov[d4 * 4], ov[d4 * 4 + 1], ov[d4 * 4 + 2], ov[d4 * 4 + 3]);
    }
}

// ---------------- final projection: q = h . c2_w + c2_b ----------------
__global__ void qout_k(const float* __restrict__ c2w,
                       const float* __restrict__ c2b,
                       float* __restrict__ out) {
    int lane = threadIdx.x & 31;
    int wid  = threadIdx.x >> 5;
    size_t row = (size_t)blockIdx.x * 8 + wid;      // 0 .. A*B-1
    int a = (int)(row >> 15);                       // B = 2^15
    float4 v = ((const float4*)(g_h + row * 128))[lane];
    float4 w = ((const float4*)(c2w + a * 128))[lane];
    float s = v.x * w.x + v.y * w.y + v.z * w.z + v.w * w.w;
    #pragma unroll
    for (int o = 16; o > 0; o >>= 1) s += __shfl_xor_sync(0xffffffffu, s, o);
    if (lane == 0) out[row] = s + c2b[a];
}

// ---------------- launch ----------------
extern "C" void kernel_launch(void* const* d_in, const int* in_sizes, int n_in,
                              void* d_out, int out_size) {
    const float* states = (const float*)d_in[0];
    const float* actions= (const float*)d_in[1];
    const float* enc_w  = (const float*)d_in[2];
    const float* enc_b  = (const float*)d_in[3];
    const float* aenc_w = (const float*)d_in[4];
    const float* aenc_b = (const float*)d_in[5];
    const float* key_w  = (const float*)d_in[6];
    const float* sel_w  = (const float*)d_in[7];
    const float* val_w  = (const float*)d_in[8];
    const float* val_b  = (const float*)d_in[9];
    const float* c1_w   = (const float*)d_in[10];
    const float* c1_b   = (const float*)d_in[11];
    const float* c2_w   = (const float*)d_in[12];
    const float* c2_b   = (const float*)d_in[13];
    float* out = (float*)d_out;

    void *p_aenc, *p_keys, *p_sels, *p_vals, *p_ci, *p_h, *p_wk, *p_ws, *p_wv;
    cudaGetSymbolAddress(&p_aenc, g_aenc);
    cudaGetSymbolAddress(&p_keys, g_keys);
    cudaGetSymbolAddress(&p_sels, g_sels);
    cudaGetSymbolAddress(&p_vals, g_vals);
    cudaGetSymbolAddress(&p_ci,   g_ci);
    cudaGetSymbolAddress(&p_h,    g_h);
    cudaGetSymbolAddress(&p_wk,   g_Wk);
    cudaGetSymbolAddress(&p_ws,   g_Ws);
    cudaGetSymbolAddress(&p_wv,   g_Wv);

    bn_partial_k<<<dim3(32, 8), 320>>>(states, actions);
    bn_final_k<<<8, 160>>>();
    pack_k<<<192, 256>>>(key_w, sel_w, val_w);

    dim3 gg(256, 1, 8);
    // sa_enc -> critic_in[:, :, 0:128]   (BN concat gen, K=160, lrelu)
    gemm_k<<<gg, 256>>>(nullptr, 0, states, actions, enc_w, 160 * 128,
                        enc_b, 128, (float*)p_ci, 256, 160, 1, 1);
    // a_enc (BN actions gen, K=32, lrelu)
    gemm_k<<<gg, 256>>>(nullptr, 0, states, actions, aenc_w, 32 * 128,
                        aenc_b, 128, (float*)p_aenc, 128, 32, 2, 1);
    // keys = a_enc @ Wk
    gemm_k<<<gg, 256>>>((const float*)p_aenc, 128, nullptr, nullptr,
                        (const float*)p_wk, 0, nullptr, 0,
                        (float*)p_keys, 128, 128, 0, 0);
    // vals = lrelu(a_enc @ Wv + val_b)
    gemm_k<<<gg, 256>>>((const float*)p_aenc, 128, nullptr, nullptr,
                        (const float*)p_wv, 0, val_b, 0,
                        (float*)p_vals, 128, 128, 0, 1);
    // sels = sa_enc @ Ws  (reads critic_in cols 0..127 with lda=256)
    gemm_k<<<gg, 256>>>((const float*)p_ci, 256, nullptr, nullptr,
                        (const float*)p_ws, 0, nullptr, 0,
                        (float*)p_sels, 128, 128, 0, 0);
    // attention -> critic_in[:, :, 128:256]
    attn_k<<<Bsz / 16, 128>>>();
    // h = lrelu(critic_in @ c1_w + c1_b), K=256
    gemm_k<<<gg, 256>>>((const float*)p_ci, 256, nullptr, nullptr,
                        c1_w, 256 * 128, c1_b, 128,
                        (float*)p_h, 128, 256, 0, 1);
    // q
    qout_k<<<Bsz, 256>>>(c2_w, c2_b, out);
}

// round 3
// speedup vs baseline: 2.3371x; 2.3371x over previous
#include <cuda_runtime.h>
#include <cuda_fp16.h>
#include <cstdint>
#include <cstddef>

#define A_   8
#define Bsz  32768
#define EPSB 1e-5f

// ---------------- static scratch ----------------
__device__ float g_part[8 * 32 * 160 * 2];
__device__ float g_mean[8 * 160];
__device__ float g_istd[8 * 160];
__device__ float g_aenc[(size_t)A_ * Bsz * 128];
__device__ float g_keys[(size_t)A_ * Bsz * 128];
__device__ float g_sels[(size_t)A_ * Bsz * 128];
__device__ float g_vals[(size_t)A_ * Bsz * 128];
__device__ float g_ci  [(size_t)A_ * Bsz * 256];     // [sa_enc | attended]
// pre-packed fp16 hi/lo weights: [agent][n][K'=2K], hi at k'=32*(k/16)+(k%16), lo +16
__device__ __half g_Benc [(size_t)8 * 128 * 320];
__device__ __half g_Baenc[(size_t)8 * 128 * 64];
__device__ __half g_Bhk  [(size_t)128 * 256];
__device__ __half g_Bhs  [(size_t)128 * 256];
__device__ __half g_Bhv  [(size_t)128 * 256];
__device__ __half g_Bc1  [(size_t)8 * 128 * 512];

__device__ __forceinline__ float lrelu(float x) { return fmaxf(x, 0.01f * x); }
__device__ __forceinline__ uint32_t smem_u32(const void* p) {
    uint32_t a;
    asm("{ .reg .u64 t; cvta.to.shared.u64 t, %1; cvt.u32.u64 %0, t; }" : "=r"(a) : "l"(p));
    return a;
}

__device__ __forceinline__ void ldsm4(uint32_t* r, uint32_t addr) {
    asm volatile("ldmatrix.sync.aligned.m8n8.x4.shared.b16 {%0,%1,%2,%3}, [%4];"
        : "=r"(r[0]), "=r"(r[1]), "=r"(r[2]), "=r"(r[3]) : "r"(addr));
}
__device__ __forceinline__ void mma16816(float* d, const uint32_t* a, const uint32_t* b) {
    asm volatile("mma.sync.aligned.m16n8k16.row.col.f32.f16.f16.f32 "
        "{%0,%1,%2,%3}, {%4,%5,%6,%7}, {%8,%9}, {%0,%1,%2,%3};"
        : "+f"(d[0]), "+f"(d[1]), "+f"(d[2]), "+f"(d[3])
        : "r"(a[0]), "r"(a[1]), "r"(a[2]), "r"(a[3]), "r"(b[0]), "r"(b[1]));
}
#define CP16(s, g) asm volatile("cp.async.cg.shared.global [%0], [%1], 16;" :: "r"(s), "l"(g))
#define CPCOMMIT() asm volatile("cp.async.commit_group;" ::: "memory")
#define CPWAIT1()  asm volatile("cp.async.wait_group 1;" ::: "memory")
#define CPWAIT0()  asm volatile("cp.async.wait_group 0;" ::: "memory")

__device__ __forceinline__ uint32_t pkh2(__half a, __half b) {
    __half2 h = __halves2half2(a, b);
    return *(uint32_t*)&h;
}

// ---------------- BatchNorm stats ----------------
__global__ void bn_partial_k(const float* __restrict__ states,
                             const float* __restrict__ actions) {
    int a = blockIdx.y, chunk = blockIdx.x;
    int t = threadIdx.x;
    int f = t % 160, r0 = t / 160;
    size_t sb = (size_t)a * Bsz * 128, ab = (size_t)a * Bsz * 32;
    int row0 = chunk * 1024;
    float s = 0.f, s2 = 0.f;
    if (f < 128) {
        const float* p = states + sb + (size_t)(row0 + r0) * 128 + f;
        #pragma unroll 4
        for (int r = 0; r < 512; r++) { float v = *p; p += 256; s += v; s2 += v * v; }
    } else {
        const float* p = actions + ab + (size_t)(row0 + r0) * 32 + (f - 128);
        #pragma unroll 4
        for (int r = 0; r < 512; r++) { float v = *p; p += 64; s += v; s2 += v * v; }
    }
    __shared__ float sh[640];
    sh[t] = s; sh[320 + t] = s2;
    __syncthreads();
    if (t < 160) {
        float ss = sh[t] + sh[t + 160];
        float qq = sh[320 + t] + sh[320 + t + 160];
        int o = ((a * 32 + chunk) * 160 + t) * 2;
        g_part[o] = ss; g_part[o + 1] = qq;
    }
}

__global__ void bn_final_k() {
    int a = blockIdx.x, f = threadIdx.x;
    float s = 0.f, s2 = 0.f;
    for (int c = 0; c < 32; c++) {
        int o = ((a * 32 + c) * 160 + f) * 2;
        s += g_part[o]; s2 += g_part[o + 1];
    }
    float m = s * (1.f / 32768.f);
    float v = s2 * (1.f / 32768.f) - m * m;
    g_mean[a * 160 + f] = m;
    g_istd[a * 160 + f] = rsqrtf(v + EPSB);
}

// ---------------- weight pack: transpose + fp16 hi/lo split ----------------
// mode 0: src [a][k][n=128]    mode 1: heads src [(n>>5)][k][n&31], blockIdx.y==0
__global__ void pack_w(const float* __restrict__ src, __half* __restrict__ dst,
                       int K, int mode) {
    __shared__ float tile[16][128];
    int a = blockIdx.y, kt = blockIdx.x, t = threadIdx.x;
    int k0 = kt * 16;
    #pragma unroll
    for (int i = 0; i < 2; i++) {
        int p = t + i * 256;
        int kk = p >> 5, n4 = (p & 31) * 4;
        float4 v;
        if (mode == 0)
            v = *(const float4*)(src + ((size_t)a * K + k0 + kk) * 128 + n4);
        else
            v = *(const float4*)(src + ((size_t)(n4 >> 5) * 128 + k0 + kk) * 32 + (n4 & 31));
        tile[kk][n4] = v.x; tile[kk][n4 + 1] = v.y;
        tile[kk][n4 + 2] = v.z; tile[kk][n4 + 3] = v.w;
    }
    __syncthreads();
    int K2 = 2 * K;
    #pragma unroll
    for (int i = 0; i < 2; i++) {
        int p = t + i * 256;
        int n = p >> 2, kq = p & 3;
        __half h[4], l[4];
        #pragma unroll
        for (int j = 0; j < 4; j++) {
            float x = tile[kq * 4 + j][n];
            h[j] = __float2half_rn(x);
            l[j] = __float2half_rn(x - __half2float(h[j]));
        }
        __half* base = dst + (size_t)a * 128 * K2 + (size_t)n * K2 + kt * 32 + kq * 4;
        uint2 uh; uh.x = pkh2(h[0], h[1]); uh.y = pkh2(h[2], h[3]);
        uint2 ul; ul.x = pkh2(l[0], l[1]); ul.y = pkh2(l[2], l[3]);
        *(uint2*)base = uh;
        *(uint2*)(base + 16) = ul;
    }
}

// ---------------- mma.sync fp16 hi/lo GEMM ----------------
// C[a][m][n] = epi( sum_k A[a][m][k] * B[n][k] [+ bias] )
// SRC: 0 direct (Abase,lda), 1 BN(concat) K=160, 2 BN(actions) K=32
// EPI: 0 raw, 1 bias+lrelu, 2 bias+lrelu then dot with c2w -> qout
#define PITCH 80
#define STAGE 20480

template<int SRC, int EPI>
__global__ __launch_bounds__(256, 2) void gemm_mma(
    const float* __restrict__ Abase, int lda,
    const float* __restrict__ states, const float* __restrict__ actions,
    const __half* __restrict__ Bt, long wstride,
    const float* __restrict__ bias, int bstride,
    float* __restrict__ C, int ldc,
    const float* __restrict__ c2w, const float* __restrict__ c2b,
    float* __restrict__ qout,
    int Kdim) {

    __shared__ __align__(16) char sm[2][STAGE];
    int tid = threadIdx.x, lane = tid & 31, wid = tid >> 5;
    int wm = wid & 3, wn = wid >> 2;
    int a = blockIdx.z, m0 = blockIdx.x * 128;
    int K2 = Kdim * 2;
    int nch = Kdim >> 4;

    const float* mp = g_mean + a * 160;
    const float* ip = g_istd + a * 160;
    size_t sbo = (size_t)a * Bsz * 128, abo = (size_t)a * Bsz * 32;
    const float* Ap = (SRC == 0) ? (Abase + (size_t)a * Bsz * lda) : nullptr;
    const __half* Bp = Bt + (size_t)a * wstride;

    uint32_t smu = smem_u32(sm);

    // producer coords
    float4 av[2];
    auto loadA = [&](int c) {
        #pragma unroll
        for (int i = 0; i < 2; i++) {
            int p = tid + i * 256;
            int row = p >> 2, kq = p & 3;
            int k = c * 16 + kq * 4;
            float4 v;
            if (SRC == 1) {
                if (k < 128) v = *(const float4*)(states + sbo + (size_t)(m0 + row) * 128 + k);
                else         v = *(const float4*)(actions + abo + (size_t)(m0 + row) * 32 + (k - 128));
                v.x = (v.x - mp[k    ]) * ip[k    ];
                v.y = (v.y - mp[k + 1]) * ip[k + 1];
                v.z = (v.z - mp[k + 2]) * ip[k + 2];
                v.w = (v.w - mp[k + 3]) * ip[k + 3];
            } else if (SRC == 2) {
                v = *(const float4*)(actions + abo + (size_t)(m0 + row) * 32 + k);
                v.x = (v.x - mp[128 + k]) * ip[128 + k];
                v.y = (v.y - mp[129 + k]) * ip[129 + k];
                v.z = (v.z - mp[130 + k]) * ip[130 + k];
                v.w = (v.w - mp[131 + k]) * ip[131 + k];
            } else {
                v = *(const float4*)(Ap + (size_t)(m0 + row) * lda + k);
            }
            av[i] = v;
        }
    };
    auto stsA = [&](int buf) {
        #pragma unroll
        for (int i = 0; i < 2; i++) {
            int p = tid + i * 256;
            int row = p >> 2, kq = p & 3;
            float4 v = av[i];
            __half h0 = __float2half_rn(v.x), h1 = __float2half_rn(v.y);
            __half h2 = __float2half_rn(v.z), h3 = __float2half_rn(v.w);
            __half l0 = __float2half_rn(v.x - __half2float(h0));
            __half l1 = __float2half_rn(v.y - __half2float(h1));
            __half l2 = __float2half_rn(v.z - __half2float(h2));
            __half l3 = __float2half_rn(v.w - __half2float(h3));
            uint2 uh; uh.x = pkh2(h0, h1); uh.y = pkh2(h2, h3);
            uint2 ul; ul.x = pkh2(l0, l1); ul.y = pkh2(l2, l3);
            char* base = sm[buf] + row * PITCH + kq * 8;
            *(uint2*)base = uh;
            *(uint2*)(base + 32) = ul;
        }
    };
    auto cpB = [&](int c, int buf) {
        #pragma unroll
        for (int i = 0; i < 2; i++) {
            int s = tid + i * 256;
            int n = s >> 2, seg = s & 3;
            const __half* g = Bp + (size_t)n * K2 + c * 32 + seg * 8;
            uint32_t sa = smu + buf * STAGE + 10240 + n * PITCH + seg * 16;
            CP16(sa, g);
        }
        CPCOMMIT();
    };

    // ldmatrix per-lane byte offsets
    int r = lane & 7, q = lane >> 3;
    uint32_t a_off[2], b_off[4];
    #pragma unroll
    for (int mt = 0; mt < 2; mt++)
        a_off[mt] = (uint32_t)((wm * 32 + mt * 16 + (q & 1) * 8 + r) * PITCH + (q >> 1) * 16);
    #pragma unroll
    for (int np = 0; np < 4; np++)
        b_off[np] = (uint32_t)(10240 + (wn * 64 + np * 16 + (q >> 1) * 8 + r) * PITCH + (q & 1) * 16);

    float acc[2][8][4];
    #pragma unroll
    for (int mt = 0; mt < 2; mt++)
        #pragma unroll
        for (int nt = 0; nt < 8; nt++)
            #pragma unroll
            for (int i = 0; i < 4; i++) acc[mt][nt][i] = 0.f;

    loadA(0);
    cpB(0, 0);

    for (int c = 0; c < nch; c++) {
        int buf = c & 1;
        if (c + 1 < nch) cpB(c + 1, buf ^ 1);
        stsA(buf);
        if (c + 1 < nch) { loadA(c + 1); CPWAIT1(); }
        else             { CPWAIT0(); }
        __syncthreads();
        uint32_t bb = smu + buf * STAGE;
        #pragma unroll
        for (int ks = 0; ks < 2; ks++) {
            uint32_t af[2][4], bf[4][4];
            #pragma unroll
            for (int mt = 0; mt < 2; mt++) ldsm4(af[mt], bb + a_off[mt] + ks * 32);
            #pragma unroll
            for (int np = 0; np < 4; np++) ldsm4(bf[np], bb + b_off[np] + ks * 32);
            #pragma unroll
            for (int mt = 0; mt < 2; mt++)
                #pragma unroll
                for (int nt = 0; nt < 8; nt++)
                    mma16816(acc[mt][nt], af[mt], &bf[nt >> 1][(nt & 1) * 2]);
        }
        __syncthreads();
    }

    int g = lane >> 2, tig = lane & 3;

    if (EPI == 2) {
        float qp[4] = {0.f, 0.f, 0.f, 0.f};
        #pragma unroll
        for (int mt = 0; mt < 2; mt++)
            #pragma unroll
            for (int nt = 0; nt < 8; nt++) {
                int col = wn * 64 + nt * 8 + 2 * tig;
                float b0 = bias[a * bstride + col], b1 = bias[a * bstride + col + 1];
                float w0 = c2w[a * 128 + col], w1 = c2w[a * 128 + col + 1];
                qp[mt * 2]     += lrelu(acc[mt][nt][0] + b0) * w0 + lrelu(acc[mt][nt][1] + b1) * w1;
                qp[mt * 2 + 1] += lrelu(acc[mt][nt][2] + b0) * w0 + lrelu(acc[mt][nt][3] + b1) * w1;
            }
        #pragma unroll
        for (int j = 0; j < 4; j++) {
            qp[j] += __shfl_xor_sync(0xffffffffu, qp[j], 1);
            qp[j] += __shfl_xor_sync(0xffffffffu, qp[j], 2);
        }
        __syncthreads();
        float* qsm = (float*)sm;
        if (tig == 0) {
            #pragma unroll
            for (int j = 0; j < 4; j++) {
                int rl = wm * 32 + (j >> 1) * 16 + (j & 1) * 8 + g;
                qsm[rl * 2 + wn] = qp[j];
            }
        }
        __syncthreads();
        if (tid < 128)
            qout[(size_t)a * Bsz + m0 + tid] = qsm[tid * 2] + qsm[tid * 2 + 1] + c2b[a];
    } else {
        #pragma unroll
        for (int mt = 0; mt < 2; mt++) {
            int m = m0 + wm * 32 + mt * 16 + g;
            #pragma unroll
            for (int nt = 0; nt < 8; nt++) {
                int col = wn * 64 + nt * 8 + 2 * tig;
                float v0 = acc[mt][nt][0], v1 = acc[mt][nt][1];
                float v2 = acc[mt][nt][2], v3 = acc[mt][nt][3];
                if (EPI == 1) {
                    float b0 = bias[a * bstride + col], b1 = bias[a * bstride + col + 1];
                    v0 = lrelu(v0 + b0); v1 = lrelu(v1 + b1);
                    v2 = lrelu(v2 + b0); v3 = lrelu(v3 + b1);
                }
                float* c0p = C + ((size_t)a * Bsz + m) * ldc + col;
                *(float2*)c0p = make_float2(v0, v1);
                *(float2*)(c0p + (size_t)8 * ldc) = make_float2(v2, v3);
            }
        }
    }
}

// ---------------- attention: 16 batch elts x 8 agents per block ----------------
__global__ __launch_bounds__(128) void attn_k() {
    __shared__ float sA[128 * 33];
    __shared__ float sK[128 * 33];
    int t = threadIdx.x;
    int b0 = blockIdx.x * 16;
    int bl = t >> 3, iq = t & 7;
    int lbl = t >> 3, lf4 = t & 7;

    for (int kh = 0; kh < 4; kh++) {
        __syncthreads();
        #pragma unroll
        for (int ag = 0; ag < 8; ag++) {
            size_t off = ((size_t)ag * Bsz + b0 + lbl) * 128 + kh * 32 + lf4 * 4;
            float4 v = *(const float4*)(g_sels + off);
            int base = (lbl * 8 + ag) * 33 + lf4 * 4;
            sA[base] = v.x; sA[base + 1] = v.y; sA[base + 2] = v.z; sA[base + 3] = v.w;
            float4 w = *(const float4*)(g_keys + off);
            sK[base] = w.x; sK[base + 1] = w.y; sK[base + 2] = w.z; sK[base + 3] = w.w;
        }
        __syncthreads();

        float sv[32];
        #pragma unroll
        for (int d = 0; d < 32; d++) sv[d] = sA[(bl * 8 + iq) * 33 + d];
        float p[8];
        #pragma unroll
        for (int j = 0; j < 8; j++) {
            float acc = 0.f;
            #pragma unroll
            for (int d = 0; d < 32; d++) acc += sv[d] * sK[(bl * 8 + j) * 33 + d];
            p[j] = acc * 0.17677669529663687f;
        }
        float mx = -1e30f;
        #pragma unroll
        for (int j = 0; j < 8; j++) if (j != iq) mx = fmaxf(mx, p[j]);
        float sum = 0.f;
        #pragma unroll
        for (int j = 0; j < 8; j++) {
            p[j] = (j == iq) ? 0.f : __expf(p[j] - mx);
            sum += p[j];
        }
        float inv = 1.f / sum;

        __syncthreads();
        #pragma unroll
        for (int ag = 0; ag < 8; ag++) {
            size_t off = ((size_t)ag * Bsz + b0 + lbl) * 128 + kh * 32 + lf4 * 4;
            float4 v = *(const float4*)(g_vals + off);
            int base = (lbl * 8 + ag) * 33 + lf4 * 4;
            sA[base] = v.x; sA[base + 1] = v.y; sA[base + 2] = v.z; sA[base + 3] = v.w;
        }
        __syncthreads();

        float ov[32];
        #pragma unroll
        for (int d = 0; d < 32; d++) ov[d] = 0.f;
        #pragma unroll
        for (int j = 0; j < 8; j++) {
            float pj = p[j] * inv;
            #pragma unroll
            for (int d = 0; d < 32; d++) ov[d] += pj * sA[(bl * 8 + j) * 33 + d];
        }
        float* dst = g_ci + ((size_t)iq * Bsz + b0 + bl) * 256 + 128 + kh * 32;
        #pragma unroll
        for (int d4 = 0; d4 < 8; d4++)
            *(float4*)(dst + d4 * 4) =
                make_float4(ov[d4 * 4], ov[d4 * 4 + 1], ov[d4 * 4 + 2], ov[d4 * 4 + 3]);
    }
}

// ---------------- launch ----------------
extern "C" void kernel_launch(void* const* d_in, const int* in_sizes, int n_in,
                              void* d_out, int out_size) {
    const float* states = (const float*)d_in[0];
    const float* actions= (const float*)d_in[1];
    const float* enc_w  = (const float*)d_in[2];
    const float* enc_b  = (const float*)d_in[3];
    const float* aenc_w = (const float*)d_in[4];
    const float* aenc_b = (const float*)d_in[5];
    const float* key_w  = (const float*)d_in[6];
    const float* sel_w  = (const float*)d_in[7];
    const float* val_w  = (const float*)d_in[8];
    const float* val_b  = (const float*)d_in[9];
    const float* c1_w   = (const float*)d_in[10];
    const float* c1_b   = (const float*)d_in[11];
    const float* c2_w   = (const float*)d_in[12];
    const float* c2_b   = (const float*)d_in[13];
    float* out = (float*)d_out;

    void *p_aenc, *p_keys, *p_sels, *p_vals, *p_ci;
    void *p_Benc, *p_Baenc, *p_Bhk, *p_Bhs, *p_Bhv, *p_Bc1;
    cudaGetSymbolAddress(&p_aenc, g_aenc);
    cudaGetSymbolAddress(&p_keys, g_keys);
    cudaGetSymbolAddress(&p_sels, g_sels);
    cudaGetSymbolAddress(&p_vals, g_vals);
    cudaGetSymbolAddress(&p_ci,   g_ci);
    cudaGetSymbolAddress(&p_Benc, g_Benc);
    cudaGetSymbolAddress(&p_Baenc,g_Baenc);
    cudaGetSymbolAddress(&p_Bhk,  g_Bhk);
    cudaGetSymbolAddress(&p_Bhs,  g_Bhs);
    cudaGetSymbolAddress(&p_Bhv,  g_Bhv);
    cudaGetSymbolAddress(&p_Bc1,  g_Bc1);

    bn_partial_k<<<dim3(32, 8), 320>>>(states, actions);
    bn_final_k<<<8, 160>>>();
    pack_w<<<dim3(10, 8), 256>>>(enc_w,  (__half*)p_Benc, 160, 0);
    pack_w<<<dim3(2, 8),  256>>>(aenc_w, (__half*)p_Baenc, 32, 0);
    pack_w<<<dim3(16, 8), 256>>>(c1_w,   (__half*)p_Bc1,  256, 0);
    pack_w<<<dim3(8, 1),  256>>>(key_w,  (__half*)p_Bhk,  128, 1);
    pack_w<<<dim3(8, 1),  256>>>(sel_w,  (__half*)p_Bhs,  128, 1);
    pack_w<<<dim3(8, 1),  256>>>(val_w,  (__half*)p_Bhv,  128, 1);

    dim3 gg(256, 1, 8);
    // sa_enc -> ci[:, 0:128]  (BN concat, K=160, bias+lrelu)
    gemm_mma<1, 1><<<gg, 256>>>(nullptr, 0, states, actions,
                                (const __half*)p_Benc, 128L * 320,
                                enc_b, 128, (float*)p_ci, 256,
                                nullptr, nullptr, nullptr, 160);
    // a_enc (BN actions, K=32, bias+lrelu)
    gemm_mma<2, 1><<<gg, 256>>>(nullptr, 0, states, actions,
                                (const __half*)p_Baenc, 128L * 64,
                                aenc_b, 128, (float*)p_aenc, 128,
                                nullptr, nullptr, nullptr, 32);
    // keys = a_enc @ Wk (raw)
    gemm_mma<0, 0><<<gg, 256>>>((const float*)p_aenc, 128, nullptr, nullptr,
                                (const __half*)p_Bhk, 0,
                                nullptr, 0, (float*)p_keys, 128,
                                nullptr, nullptr, nullptr, 128);
    // vals = lrelu(a_enc @ Wv + val_b)  (shared bias, bstride=0)
    gemm_mma<0, 1><<<gg, 256>>>((const float*)p_aenc, 128, nullptr, nullptr,
                                (const __half*)p_Bhv, 0,
                                val_b, 0, (float*)p_vals, 128,
                                nullptr, nullptr, nullptr, 128);
    // sels = sa_enc @ Ws  (A = ci cols 0..127, lda=256)
    gemm_mma<0, 0><<<gg, 256>>>((const float*)p_ci, 256, nullptr, nullptr,
                                (const __half*)p_Bhs, 0,
                                nullptr, 0, (float*)p_sels, 128,
                                nullptr, nullptr, nullptr, 128);
    // attention -> ci[:, 128:256]
    attn_k<<<Bsz / 16, 128>>>();
    // c1 + q fused
    gemm_mma<0, 2><<<gg, 256>>>((const float*)p_ci, 256, nullptr, nullptr,
                                (const __half*)p_Bc1, 128L * 512,
                                c1_b, 128, nullptr, 0,
                                c2_w, c2_b, out, 256);
}

// round 4
// speedup vs baseline: 2.4710x; 1.0573x over previous
#include <cuda_runtime.h>
#include <cuda_fp16.h>
#include <cstdint>
#include <cstddef>

#define A_   8
#define Bsz  32768
#define EPSB 1e-5f

// ---------------- static scratch ----------------
__device__ float g_part[8 * 32 * 160 * 2];
__device__ float g_mean[8 * 160];
__device__ float g_istd[8 * 160];
// pre-split (hi,lo) fp16 pairs, 1 uint32 per element (value = hi+lo)
__device__ __align__(128) uint32_t g_aenc[(size_t)A_ * Bsz * 128];
__device__ __align__(128) uint32_t g_ci  [(size_t)A_ * Bsz * 256];  // [sa_enc | attended]
// plain fp16 tensors for attention
__device__ __align__(128) __half g_keysh[(size_t)A_ * Bsz * 128];
__device__ __align__(128) __half g_selsh[(size_t)A_ * Bsz * 128];
__device__ __align__(128) __half g_valsh[(size_t)A_ * Bsz * 128];
// packed fp16 weights, [agent][n][K'=2K], value duplicated in both k' slots (B-dup)
__device__ __align__(128) __half g_Benc [(size_t)8 * 128 * 320];
__device__ __align__(128) __half g_Baenc[(size_t)8 * 128 * 64];
__device__ __align__(128) __half g_Bhk  [(size_t)128 * 256];
__device__ __align__(128) __half g_Bhs  [(size_t)128 * 256];
__device__ __align__(128) __half g_Bhv  [(size_t)128 * 256];
__device__ __align__(128) __half g_Bc1  [(size_t)8 * 128 * 512];

__device__ __forceinline__ float lrelu(float x) { return fmaxf(x, 0.01f * x); }
__device__ __forceinline__ uint32_t smem_u32(const void* p) {
    uint32_t a;
    asm("{ .reg .u64 t; cvta.to.shared.u64 t, %1; cvt.u32.u64 %0, t; }" : "=r"(a) : "l"(p));
    return a;
}
__device__ __forceinline__ void ldsm4(uint32_t* r, uint32_t addr) {
    asm volatile("ldmatrix.sync.aligned.m8n8.x4.shared.b16 {%0,%1,%2,%3}, [%4];"
        : "=r"(r[0]), "=r"(r[1]), "=r"(r[2]), "=r"(r[3]) : "r"(addr));
}
__device__ __forceinline__ void mma16816(float* d, const uint32_t* a, const uint32_t* b) {
    asm volatile("mma.sync.aligned.m16n8k16.row.col.f32.f16.f16.f32 "
        "{%0,%1,%2,%3}, {%4,%5,%6,%7}, {%8,%9}, {%0,%1,%2,%3};"
        : "+f"(d[0]), "+f"(d[1]), "+f"(d[2]), "+f"(d[3])
        : "r"(a[0]), "r"(a[1]), "r"(a[2]), "r"(a[3]), "r"(b[0]), "r"(b[1]));
}
#define CP16(s, g) asm volatile("cp.async.cg.shared.global [%0], [%1], 16;" :: "r"(s), "l"(g))
#define CPCOMMIT() asm volatile("cp.async.commit_group;" ::: "memory")
#define CPWAIT1()  asm volatile("cp.async.wait_group 1;" ::: "memory")
#define CPWAIT0()  asm volatile("cp.async.wait_group 0;" ::: "memory")

__device__ __forceinline__ uint32_t pkh2(__half a, __half b) {
    __half2 h = __halves2half2(a, b);
    return *(uint32_t*)&h;
}
// split x -> packed (hi, lo) fp16 pair
__device__ __forceinline__ uint32_t splitpk(float x) {
    __half h = __float2half_rn(x);
    __half l = __float2half_rn(x - __half2float(h));
    return pkh2(h, l);
}

// ---------------- BatchNorm stats ----------------
__global__ void bn_partial_k(const float* __restrict__ states,
                             const float* __restrict__ actions) {
    int a = blockIdx.y, chunk = blockIdx.x;
    int t = threadIdx.x;
    int f = t % 160, r0 = t / 160;
    size_t sb = (size_t)a * Bsz * 128, ab = (size_t)a * Bsz * 32;
    int row0 = chunk * 1024;
    float s = 0.f, s2 = 0.f;
    if (f < 128) {
        const float* p = states + sb + (size_t)(row0 + r0) * 128 + f;
        #pragma unroll 4
        for (int r = 0; r < 512; r++) { float v = *p; p += 256; s += v; s2 += v * v; }
    } else {
        const float* p = actions + ab + (size_t)(row0 + r0) * 32 + (f - 128);
        #pragma unroll 4
        for (int r = 0; r < 512; r++) { float v = *p; p += 64; s += v; s2 += v * v; }
    }
    __shared__ float sh[640];
    sh[t] = s; sh[320 + t] = s2;
    __syncthreads();
    if (t < 160) {
        float ss = sh[t] + sh[t + 160];
        float qq = sh[320 + t] + sh[320 + t + 160];
        int o = ((a * 32 + chunk) * 160 + t) * 2;
        g_part[o] = ss; g_part[o + 1] = qq;
    }
}

__global__ void bn_final_k() {
    int a = blockIdx.x, f = threadIdx.x;
    float s = 0.f, s2 = 0.f;
    for (int c = 0; c < 32; c++) {
        int o = ((a * 32 + c) * 160 + f) * 2;
        s += g_part[o]; s2 += g_part[o + 1];
    }
    float m = s * (1.f / 32768.f);
    float v = s2 * (1.f / 32768.f) - m * m;
    g_mean[a * 160 + f] = m;
    g_istd[a * 160 + f] = rsqrtf(v + EPSB);
}

// ---------------- weight pack: transpose + fp16 + duplicate (B-dup) ----------------
// mode 0: src [a][k][n=128]    mode 1: heads src [(n>>5)][k][n&31]
__global__ void pack_w(const float* __restrict__ src, __half* __restrict__ dst,
                       int K, int mode) {
    __shared__ float tile[16][128];
    int a = blockIdx.y, kt = blockIdx.x, t = threadIdx.x;
    int k0 = kt * 16;
    #pragma unroll
    for (int i = 0; i < 2; i++) {
        int p = t + i * 256;
        int kk = p >> 5, n4 = (p & 31) * 4;
        float4 v;
        if (mode == 0)
            v = *(const float4*)(src + ((size_t)a * K + k0 + kk) * 128 + n4);
        else
            v = *(const float4*)(src + ((size_t)(n4 >> 5) * 128 + k0 + kk) * 32 + (n4 & 31));
        tile[kk][n4] = v.x; tile[kk][n4 + 1] = v.y;
        tile[kk][n4 + 2] = v.z; tile[kk][n4 + 3] = v.w;
    }
    __syncthreads();
    int K2 = 2 * K;
    #pragma unroll
    for (int i = 0; i < 2; i++) {
        int p = t + i * 256;
        int n = p >> 2, kq = p & 3;
        __half h[4];
        #pragma unroll
        for (int j = 0; j < 4; j++)
            h[j] = __float2half_rn(tile[kq * 4 + j][n]);
        // value k at k'=2k and 2k+1 (interleaved dup)
        uint4 u;
        u.x = pkh2(h[0], h[0]); u.y = pkh2(h[1], h[1]);
        u.z = pkh2(h[2], h[2]); u.w = pkh2(h[3], h[3]);
        *(uint4*)(dst + (size_t)a * 128 * K2 + (size_t)n * K2 + kt * 32 + kq * 8) = u;
    }
}

// ---------------- mma.sync split GEMM (A = h+l exact, B = hi dup) ----------------
// C[a][m][n] = epi( sum_k A[a][m][k] * B[n][k] [+ bias] )
// SRC: 0 pre-split pairs via cp.async (Apairs,lda), 1 BN(concat) K=160, 2 BN(actions) K=32
// EPI: 0 raw fp16, 1 bias+lrelu -> pairs, 2 bias+lrelu + c2 dot -> qout, 3 bias+lrelu fp16
#define PITCH 80
#define STAGE 20480

template<int SRC, int EPI>
__global__ __launch_bounds__(256, 2) void gemm_mma(
    const uint32_t* __restrict__ Apairs, int lda,
    const float* __restrict__ states, const float* __restrict__ actions,
    const __half* __restrict__ Bt, long wstride,
    const float* __restrict__ bias, int bstride,
    void* __restrict__ Cout, int ldc,
    const float* __restrict__ c2w, const float* __restrict__ c2b,
    float* __restrict__ qout,
    int Kdim) {

    __shared__ __align__(16) char sm[2][STAGE];
    int tid = threadIdx.x, lane = tid & 31, wid = tid >> 5;
    int wm = wid & 3, wn = wid >> 2;
    int a = blockIdx.z, m0 = blockIdx.x * 128;
    int K2 = Kdim * 2;
    int nch = Kdim >> 4;

    const float* mp = g_mean + a * 160;
    const float* ip = g_istd + a * 160;
    size_t sbo = (size_t)a * Bsz * 128, abo = (size_t)a * Bsz * 32;
    const uint32_t* Ap = (SRC == 0) ? (Apairs + (size_t)a * Bsz * lda) : nullptr;
    const __half* Bp = Bt + (size_t)a * wstride;

    uint32_t smu = smem_u32(sm);

    float4 av[2];
    auto loadA = [&](int c) {
        #pragma unroll
        for (int i = 0; i < 2; i++) {
            int p = tid + i * 256;
            int row = p >> 2, kq = p & 3;
            int k = c * 16 + kq * 4;
            float4 v;
            if (SRC == 1) {
                if (k < 128) v = *(const float4*)(states + sbo + (size_t)(m0 + row) * 128 + k);
                else         v = *(const float4*)(actions + abo + (size_t)(m0 + row) * 32 + (k - 128));
                v.x = (v.x - mp[k    ]) * ip[k    ];
                v.y = (v.y - mp[k + 1]) * ip[k + 1];
                v.z = (v.z - mp[k + 2]) * ip[k + 2];
                v.w = (v.w - mp[k + 3]) * ip[k + 3];
            } else {
                v = *(const float4*)(actions + abo + (size_t)(m0 + row) * 32 + k);
                v.x = (v.x - mp[128 + k]) * ip[128 + k];
                v.y = (v.y - mp[129 + k]) * ip[129 + k];
                v.z = (v.z - mp[130 + k]) * ip[130 + k];
                v.w = (v.w - mp[131 + k]) * ip[131 + k];
            }
            av[i] = v;
        }
    };
    auto stsA = [&](int buf) {
        #pragma unroll
        for (int i = 0; i < 2; i++) {
            int p = tid + i * 256;
            int row = p >> 2, kq = p & 3;
            float4 v = av[i];
            uint4 u;
            u.x = splitpk(v.x); u.y = splitpk(v.y);
            u.z = splitpk(v.z); u.w = splitpk(v.w);
            *(uint4*)(sm[buf] + row * PITCH + kq * 16) = u;
        }
    };
    // cp.async producers
    auto cpA = [&](int c, int buf) {
        #pragma unroll
        for (int i = 0; i < 2; i++) {
            int p = tid + i * 256;
            int row = p >> 2, seg = p & 3;
            const uint32_t* g = Ap + (size_t)(m0 + row) * lda + c * 16 + seg * 4;
            uint32_t sa = smu + buf * STAGE + row * PITCH + seg * 16;
            CP16(sa, g);
        }
    };
    auto cpB = [&](int c, int buf) {
        #pragma unroll
        for (int i = 0; i < 2; i++) {
            int s = tid + i * 256;
            int n = s >> 2, seg = s & 3;
            const __half* g = Bp + (size_t)n * K2 + c * 32 + seg * 8;
            uint32_t sa = smu + buf * STAGE + 10240 + n * PITCH + seg * 16;
            CP16(sa, g);
        }
    };

    // ldmatrix per-lane byte offsets (geometry unchanged from passing version)
    int r = lane & 7, q = lane >> 3;
    uint32_t a_off[2], b_off[4];
    #pragma unroll
    for (int mt = 0; mt < 2; mt++)
        a_off[mt] = (uint32_t)((wm * 32 + mt * 16 + (q & 1) * 8 + r) * PITCH + (q >> 1) * 16);
    #pragma unroll
    for (int np = 0; np < 4; np++)
        b_off[np] = (uint32_t)(10240 + (wn * 64 + np * 16 + (q >> 1) * 8 + r) * PITCH + (q & 1) * 16);

    float acc[2][8][4];
    #pragma unroll
    for (int mt = 0; mt < 2; mt++)
        #pragma unroll
        for (int nt = 0; nt < 8; nt++)
            #pragma unroll
            for (int i = 0; i < 4; i++) acc[mt][nt][i] = 0.f;

    if (SRC == 0) {
        cpA(0, 0); cpB(0, 0); CPCOMMIT();
    } else {
        loadA(0); cpB(0, 0); CPCOMMIT();
    }

    for (int c = 0; c < nch; c++) {
        int buf = c & 1;
        if (SRC == 0) {
            if (c + 1 < nch) { cpA(c + 1, buf ^ 1); cpB(c + 1, buf ^ 1); CPCOMMIT(); CPWAIT1(); }
            else             { CPWAIT0(); }
        } else {
            if (c + 1 < nch) { cpB(c + 1, buf ^ 1); CPCOMMIT(); }
            stsA(buf);
            if (c + 1 < nch) { loadA(c + 1); CPWAIT1(); }
            else             { CPWAIT0(); }
        }
        __syncthreads();
        uint32_t bb = smu + buf * STAGE;
        #pragma unroll
        for (int ks = 0; ks < 2; ks++) {
            uint32_t af[2][4], bf[4][4];
            #pragma unroll
            for (int mt = 0; mt < 2; mt++) ldsm4(af[mt], bb + a_off[mt] + ks * 32);
            #pragma unroll
            for (int np = 0; np < 4; np++) ldsm4(bf[np], bb + b_off[np] + ks * 32);
            #pragma unroll
            for (int mt = 0; mt < 2; mt++)
                #pragma unroll
                for (int nt = 0; nt < 8; nt++)
                    mma16816(acc[mt][nt], af[mt], &bf[nt >> 1][(nt & 1) * 2]);
        }
        __syncthreads();
    }

    int g = lane >> 2, tig = lane & 3;

    if (EPI == 2) {
        float qp[4] = {0.f, 0.f, 0.f, 0.f};
        #pragma unroll
        for (int mt = 0; mt < 2; mt++)
            #pragma unroll
            for (int nt = 0; nt < 8; nt++) {
                int col = wn * 64 + nt * 8 + 2 * tig;
                float b0 = bias[a * bstride + col], b1 = bias[a * bstride + col + 1];
                float w0 = c2w[a * 128 + col], w1 = c2w[a * 128 + col + 1];
                qp[mt * 2]     += lrelu(acc[mt][nt][0] + b0) * w0 + lrelu(acc[mt][nt][1] + b1) * w1;
                qp[mt * 2 + 1] += lrelu(acc[mt][nt][2] + b0) * w0 + lrelu(acc[mt][nt][3] + b1) * w1;
            }
        #pragma unroll
        for (int j = 0; j < 4; j++) {
            qp[j] += __shfl_xor_sync(0xffffffffu, qp[j], 1);
            qp[j] += __shfl_xor_sync(0xffffffffu, qp[j], 2);
        }
        __syncthreads();
        float* qsm = (float*)sm;
        if (tig == 0) {
            #pragma unroll
            for (int j = 0; j < 4; j++) {
                int rl = wm * 32 + (j >> 1) * 16 + (j & 1) * 8 + g;
                qsm[rl * 2 + wn] = qp[j];
            }
        }
        __syncthreads();
        if (tid < 128)
            qout[(size_t)a * Bsz + m0 + tid] = qsm[tid * 2] + qsm[tid * 2 + 1] + c2b[a];
    } else {
        #pragma unroll
        for (int mt = 0; mt < 2; mt++) {
            int m = m0 + wm * 32 + mt * 16 + g;
            #pragma unroll
            for (int nt = 0; nt < 8; nt++) {
                int col = wn * 64 + nt * 8 + 2 * tig;
                float v0 = acc[mt][nt][0], v1 = acc[mt][nt][1];
                float v2 = acc[mt][nt][2], v3 = acc[mt][nt][3];
                if (EPI == 1 || EPI == 3) {
                    float b0 = bias[a * bstride + col], b1 = bias[a * bstride + col + 1];
                    v0 = lrelu(v0 + b0); v1 = lrelu(v1 + b1);
                    v2 = lrelu(v2 + b0); v3 = lrelu(v3 + b1);
                }
                if (EPI == 1) {
                    uint32_t* Cp = (uint32_t*)Cout;
                    uint2 u0; u0.x = splitpk(v0); u0.y = splitpk(v1);
                    uint2 u1; u1.x = splitpk(v2); u1.y = splitpk(v3);
                    *(uint2*)(Cp + ((size_t)a * Bsz + m) * ldc + col) = u0;
                    *(uint2*)(Cp + ((size_t)a * Bsz + m + 8) * ldc + col) = u1;
                } else {
                    __half* Cp = (__half*)Cout;
                    *(__half2*)(Cp + ((size_t)a * Bsz + m) * ldc + col) = __floats2half2_rn(v0, v1);
                    *(__half2*)(Cp + ((size_t)a * Bsz + m + 8) * ldc + col) = __floats2half2_rn(v2, v3);
                }
            }
        }
    }
}

// ---------------- attention: 16 batch elts x 8 agents per block, fp16 in, pairs out ----
#define APITCH 36
__global__ __launch_bounds__(128) void attn_k() {
    __shared__ __half sS[128 * APITCH];   // sels, reused for vals
    __shared__ __half sK[128 * APITCH];   // keys
    int t = threadIdx.x;
    int b0 = blockIdx.x * 16;
    int bl = t >> 3, iq = t & 7;

    for (int kh = 0; kh < 4; kh++) {
        __syncthreads();
        {   // each thread loads one (bl, ag) row: 32 halves = 64 B per tensor
            int lbl = t >> 3, ag = t & 7;
            size_t off = ((size_t)ag * Bsz + b0 + lbl) * 128 + kh * 32;
            const uint2* ps = (const uint2*)(g_selsh + off);
            const uint2* pk = (const uint2*)(g_keysh + off);
            uint2* ds = (uint2*)(sS + (lbl * 8 + ag) * APITCH);
            uint2* dk = (uint2*)(sK + (lbl * 8 + ag) * APITCH);
            #pragma unroll
            for (int j = 0; j < 8; j++) { ds[j] = ps[j]; dk[j] = pk[j]; }
        }
        __syncthreads();

        float sv[32];
        {
            const __half2* p = (const __half2*)(sS + (bl * 8 + iq) * APITCH);
            #pragma unroll
            for (int d = 0; d < 16; d++) {
                float2 f = __half22float2(p[d]);
                sv[2 * d] = f.x; sv[2 * d + 1] = f.y;
            }
        }
        float pj[8];
        #pragma unroll
        for (int j = 0; j < 8; j++) {
            const __half2* p = (const __half2*)(sK + (bl * 8 + j) * APITCH);
            float acc = 0.f;
            #pragma unroll
            for (int d = 0; d < 16; d++) {
                float2 f = __half22float2(p[d]);
                acc += sv[2 * d] * f.x + sv[2 * d + 1] * f.y;
            }
            pj[j] = acc * 0.17677669529663687f;   // 1/sqrt(32)
        }
        float mx = -1e30f;
        #pragma unroll
        for (int j = 0; j < 8; j++) if (j != iq) mx = fmaxf(mx, pj[j]);
        float sum = 0.f;
        #pragma unroll
        for (int j = 0; j < 8; j++) {
            pj[j] = (j == iq) ? 0.f : __expf(pj[j] - mx);
            sum += pj[j];
        }
        float inv = 1.f / sum;

        __syncthreads();
        {   // reload vals into sS
            int lbl = t >> 3, ag = t & 7;
            size_t off = ((size_t)ag * Bsz + b0 + lbl) * 128 + kh * 32;
            const uint2* pv = (const uint2*)(g_valsh + off);
            uint2* ds = (uint2*)(sS + (lbl * 8 + ag) * APITCH);
            #pragma unroll
            for (int j = 0; j < 8; j++) ds[j] = pv[j];
        }
        __syncthreads();

        float ov[32];
        #pragma unroll
        for (int d = 0; d < 32; d++) ov[d] = 0.f;
        #pragma unroll
        for (int j = 0; j < 8; j++) {
            float w = pj[j] * inv;
            const __half2* p = (const __half2*)(sS + (bl * 8 + j) * APITCH);
            #pragma unroll
            for (int d = 0; d < 16; d++) {
                float2 f = __half22float2(p[d]);
                ov[2 * d]     += w * f.x;
                ov[2 * d + 1] += w * f.y;
            }
        }
        uint32_t* dst = g_ci + ((size_t)iq * Bsz + b0 + bl) * 256 + 128 + kh * 32;
        #pragma unroll
        for (int d4 = 0; d4 < 8; d4++) {
            uint4 u;
            u.x = splitpk(ov[d4 * 4]);     u.y = splitpk(ov[d4 * 4 + 1]);
            u.z = splitpk(ov[d4 * 4 + 2]); u.w = splitpk(ov[d4 * 4 + 3]);
            *(uint4*)(dst + d4 * 4) = u;
        }
    }
}

// ---------------- launch ----------------
extern "C" void kernel_launch(void* const* d_in, const int* in_sizes, int n_in,
                              void* d_out, int out_size) {
    const float* states = (const float*)d_in[0];
    const float* actions= (const float*)d_in[1];
    const float* enc_w  = (const float*)d_in[2];
    const float* enc_b  = (const float*)d_in[3];
    const float* aenc_w = (const float*)d_in[4];
    const float* aenc_b = (const float*)d_in[5];
    const float* key_w  = (const float*)d_in[6];
    const float* sel_w  = (const float*)d_in[7];
    const float* val_w  = (const float*)d_in[8];
    const float* val_b  = (const float*)d_in[9];
    const float* c1_w   = (const float*)d_in[10];
    const float* c1_b   = (const float*)d_in[11];
    const float* c2_w   = (const float*)d_in[12];
    const float* c2_b   = (const float*)d_in[13];
    float* out = (float*)d_out;

    void *p_aenc, *p_ci, *p_keysh, *p_selsh, *p_valsh;
    void *p_Benc, *p_Baenc, *p_Bhk, *p_Bhs, *p_Bhv, *p_Bc1;
    cudaGetSymbolAddress(&p_aenc, g_aenc);
    cudaGetSymbolAddress(&p_ci,   g_ci);
    cudaGetSymbolAddress(&p_keysh,g_keysh);
    cudaGetSymbolAddress(&p_selsh,g_selsh);
    cudaGetSymbolAddress(&p_valsh,g_valsh);
    cudaGetSymbolAddress(&p_Benc, g_Benc);
    cudaGetSymbolAddress(&p_Baenc,g_Baenc);
    cudaGetSymbolAddress(&p_Bhk,  g_Bhk);
    cudaGetSymbolAddress(&p_Bhs,  g_Bhs);
    cudaGetSymbolAddress(&p_Bhv,  g_Bhv);
    cudaGetSymbolAddress(&p_Bc1,  g_Bc1);

    bn_partial_k<<<dim3(32, 8), 320>>>(states, actions);
    bn_final_k<<<8, 160>>>();
    pack_w<<<dim3(10, 8), 256>>>(enc_w,  (__half*)p_Benc, 160, 0);
    pack_w<<<dim3(2, 8),  256>>>(aenc_w, (__half*)p_Baenc, 32, 0);
    pack_w<<<dim3(16, 8), 256>>>(c1_w,   (__half*)p_Bc1,  256, 0);
    pack_w<<<dim3(8, 1),  256>>>(key_w,  (__half*)p_Bhk,  128, 1);
    pack_w<<<dim3(8, 1),  256>>>(sel_w,  (__half*)p_Bhs,  128, 1);
    pack_w<<<dim3(8, 1),  256>>>(val_w,  (__half*)p_Bhv,  128, 1);

    dim3 gg(256, 1, 8);
    // sa_enc -> ci[:, 0:128] as pairs  (BN concat, K=160, bias+lrelu)
    gemm_mma<1, 1><<<gg, 256>>>(nullptr, 0, states, actions,
                                (const __half*)p_Benc, 128L * 320,
                                enc_b, 128, p_ci, 256,
                                nullptr, nullptr, nullptr, 160);
    // a_enc as pairs (BN actions, K=32, bias+lrelu)
    gemm_mma<2, 1><<<gg, 256>>>(nullptr, 0, states, actions,
                                (const __half*)p_Baenc, 128L * 64,
                                aenc_b, 128, p_aenc, 128,
                                nullptr, nullptr, nullptr, 32);
    // keys = a_enc @ Wk -> fp16
    gemm_mma<0, 0><<<gg, 256>>>((const uint32_t*)p_aenc, 128, nullptr, nullptr,
                                (const __half*)p_Bhk, 0,
                                nullptr, 0, p_keysh, 128,
                                nullptr, nullptr, nullptr, 128);
    // vals = lrelu(a_enc @ Wv + val_b) -> fp16
    gemm_mma<0, 3><<<gg, 256>>>((const uint32_t*)p_aenc, 128, nullptr, nullptr,
                                (const __half*)p_Bhv, 0,
                                val_b, 0, p_valsh, 128,
                                nullptr, nullptr, nullptr, 128);
    // sels = sa_enc @ Ws -> fp16  (A = ci pairs cols 0..127, lda=256)
    gemm_mma<0, 0><<<gg, 256>>>((const uint32_t*)p_ci, 256, nullptr, nullptr,
                                (const __half*)p_Bhs, 0,
                                nullptr, 0, p_selsh, 128,
                                nullptr, nullptr, nullptr, 128);
    // attention -> ci[:, 128:256] as pairs
    attn_k<<<Bsz / 16, 128>>>();
    // c1 + q fused (A = ci pairs, K=256)
    gemm_mma<0, 2><<<gg, 256>>>((const uint32_t*)p_ci, 256, nullptr, nullptr,
                                (const __half*)p_Bc1, 128L * 512,
                                c1_b, 128, nullptr, 0,
                                c2_w, c2_b, out, 256);
}